// round 13
// baseline (speedup 1.0000x reference)
#include <cuda_runtime.h>
#include <cuda_fp16.h>

#define NN 200000
#define NE 3200000
#define F  30
#define FS 32          // padded feature stride
#define PAD 64         // padded CSR slots per node (max deg ~36 for Poisson(16))
#define NBLK 1184      // persistent grid (8 blocks/SM x 148 SMs)

// ---- scratch (device globals; no allocation allowed) ----
__device__ int    g_is64;
__device__ int    g_deg[NN];
__device__ int    g_cursor[NN];
__device__ float  g_dinv[NN];
__device__ float  g_xs[NN * 2];      // x * dinv (layer-1 aggregation operand)
__device__ float  g_sum[NN * 2];     // edge-aggregated xs (layer 1, via atomics)
__device__ int    g_csr[NN * PAD];   // padded CSR: node d owns [d*PAD, d*PAD+deg)
__device__ __half g_feat[NN * FS];   // layer-2 pre-scaled features (fp16, 64B rows)
__device__ float  g_scal[NN];        // layer-3 scalar features

// ---------------- init: zero deg/sum + dtype detect ----------------

__global__ void k_init(const void* __restrict__ ei, int E) {
    int i = blockIdx.x * blockDim.x + threadIdx.x;
    if (i < NN) {
        g_deg[i] = 0;
        g_sum[2 * i] = 0.f;
        g_sum[2 * i + 1] = 0.f;
    }
    if (i == 0) {
        const long long* p = (const long long*)ei;
        int ok64 = 1;
        int n = (E < 64) ? E : 64;
        for (int k = 0; k < n; k++) {
            long long v = p[k];
            if (v < 0 || v >= NN) { ok64 = 0; break; }
        }
        g_is64 = ok64;
    }
}

// ---------------- histogram (dst degrees) ----------------

__global__ void k_hist(const void* __restrict__ ei, int E) {
    int is64 = g_is64;
    const long long* p64 = (const long long*)ei;
    const int*       p32 = (const int*)ei;
    for (int e = blockIdx.x * blockDim.x + threadIdx.x; e < E;
         e += gridDim.x * blockDim.x) {
        int d = is64 ? (int)p64[E + e] : p32[E + e];
        if ((unsigned)d >= NN) d = 0;
        atomicAdd(&g_deg[d], 1);
    }
}

// ---------------- finalize: cursor, dinv, xs ----------------

__global__ void k_fin(const float* __restrict__ x) {
    int i = blockIdx.x * blockDim.x + threadIdx.x;
    if (i >= NN) return;
    g_cursor[i] = i * PAD;
    int dg = g_deg[i];
    float di = rsqrtf((float)(dg + 1));   // +1 self-loop
    g_dinv[i] = di;
    g_xs[2 * i]     = x[2 * i]     * di;
    g_xs[2 * i + 1] = x[2 * i + 1] * di;
}

// ------ scatter: CSR build + edge-centric layer-1 aggregation (atomics) ----

__global__ void k_scatter(const void* __restrict__ ei, int E) {
    int is64 = g_is64;
    const long long* p64 = (const long long*)ei;
    const int*       p32 = (const int*)ei;
    for (int e = blockIdx.x * blockDim.x + threadIdx.x; e < E;
         e += gridDim.x * blockDim.x) {
        int s, d;
        if (is64) { s = (int)p64[e]; d = (int)p64[E + e]; }
        else      { s = p32[e];      d = p32[E + e]; }
        if ((unsigned)s >= NN) s = 0;
        if ((unsigned)d >= NN) d = 0;
        int pos = atomicAdd(&g_cursor[d], 1);
        if (pos < (d + 1) * PAD) g_csr[pos] = s;   // overflow guard (p ~ 0)
        float2 v = ((const float2*)g_xs)[s];
        atomicAdd(&g_sum[2 * d],     v.x);
        atomicAdd(&g_sum[2 * d + 1], v.y);
    }
}

// ------- layer 1 transform (no gather) + fused layer-2 transform -----------

// s = (g_sum[d] + xs[d]) * dinv[d]
// cat[d] = [relu(s @ W1 + b1) (30), x[d] (2)]   (registers)
// g_feat[d] = fp16( (cat[d] @ W2) * dinv[d] )   (written)
__global__ void __launch_bounds__(256)
k_l1(const float* __restrict__ x, const float* __restrict__ W1,
     const float* __restrict__ b1, const float* __restrict__ W2) {
    __shared__ float w1[64];
    __shared__ float bb[32];
    __shared__ float w2[32 * 30];
    if (threadIdx.x < 60) w1[threadIdx.x] = W1[threadIdx.x];
    if (threadIdx.x < 30) bb[threadIdx.x] = b1[threadIdx.x];
    for (int j = threadIdx.x; j < 960; j += blockDim.x) w2[j] = W2[j];
    __syncthreads();

    int w = threadIdx.x >> 5;
    int lane = threadIdx.x & 31;
    int f = (lane < F) ? lane : 0;

    for (int d = (blockIdx.x << 3) + w; d < NN; d += (NBLK << 3)) {
        float2 sm   = ((const float2*)g_sum)[d];   // uniform (broadcast) loads
        float2 self = ((const float2*)g_xs)[d];
        float  di   = g_dinv[d];
        float s0 = (sm.x + self.x) * di;
        float s1 = (sm.y + self.y) * di;

        float cat;
        if (lane < F) cat = fmaxf(fmaf(s0, w1[lane], fmaf(s1, w1[30 + lane], bb[lane])), 0.f);
        else          cat = x[2 * d + (lane - 30)];

        float acc = 0.f;
#pragma unroll
        for (int k = 0; k < 32; k++) {
            float ck = __shfl_sync(0xffffffffu, cat, k);
            acc = fmaf(ck, w2[k * 30 + f], acc);
        }
        g_feat[d * FS + lane] = __float2half((lane < F) ? acc * di : 0.f);
    }
}

// ---------------- layer 2 agg (persistent, smem idx) + layer-3 transform ---

// cat2[d] = [relu(dinv*(sum g_feat[s] + g_feat[d]) + b2) (30), x[d] (2)]  (regs)
// g_scal[d] = (cat2[d] @ W3) * dinv[d]                                     (written)
__global__ void __launch_bounds__(256)
k_agg2(const float* __restrict__ x, const float* __restrict__ b2,
       const float* __restrict__ W3) {
    __shared__ float bb[32];
    __shared__ float w3[32];
    __shared__ int   sidx[8][PAD];
    if (threadIdx.x < 30) bb[threadIdx.x] = b2[threadIdx.x];
    if (threadIdx.x < 32) w3[threadIdx.x] = W3[threadIdx.x];
    __syncthreads();

    int w = threadIdx.x >> 5;
    int lane = threadIdx.x & 31;

    for (int d = (blockIdx.x << 3) + w; d < NN; d += (NBLK << 3)) {
        int start = d * PAD, cnt = g_deg[d];
        if (lane < cnt) sidx[w][lane] = g_csr[start + lane];
        if (lane + 32 < cnt) sidx[w][lane + 32] = g_csr[start + lane + 32];
        __syncwarp();

        float acc0 = __half2float(g_feat[d * FS + lane]);   // self-loop term
        float acc1 = 0.f;
        int j = 0;
        for (; j + 1 < cnt; j += 2) {
            int s0 = sidx[w][j];
            int s1 = sidx[w][j + 1];
            acc0 += __half2float(g_feat[s0 * FS + lane]);
            acc1 += __half2float(g_feat[s1 * FS + lane]);
        }
        if (j < cnt) acc0 += __half2float(g_feat[sidx[w][j] * FS + lane]);
        float acc = acc0 + acc1;

        float di = g_dinv[d];
        float cat;
        if (lane < F) cat = fmaxf(fmaf(acc, di, bb[lane]), 0.f);
        else          cat = x[2 * d + (lane - 30)];

        float p = cat * w3[lane];
#pragma unroll
        for (int st = 16; st > 0; st >>= 1)
            p += __shfl_xor_sync(0xffffffffu, p, st);
        if (lane == 0) g_scal[d] = p * di;
        __syncwarp();
    }
}

// ---------------- layer 3 aggregation (16-lane group per node) -------------

__global__ void k_agg3(const float* __restrict__ b3, float* __restrict__ out) {
    int d = (blockIdx.x * blockDim.x + threadIdx.x) >> 4;
    int lane = threadIdx.x & 15;
    int gb = threadIdx.x & 16;
    unsigned gmask = 0xffffu << gb;
    if (d >= NN) return;
    int start = d * PAD, cnt = g_deg[d];
    float acc = 0.f;
    for (int idx = lane; idx < cnt; idx += 16)
        acc += g_scal[g_csr[start + idx]];
#pragma unroll
    for (int st = 8; st > 0; st >>= 1)
        acc += __shfl_xor_sync(gmask, acc, st);
    if (lane == 0) out[d] = g_dinv[d] * (acc + g_scal[d]) + b3[0];
}

// ---------------- launch ----------------

extern "C" void kernel_launch(void* const* d_in, const int* in_sizes, int n_in,
                              void* d_out, int out_size) {
    const float* x  = (const float*)d_in[0];
    const void*  ei = d_in[1];
    const float* W1 = (const float*)d_in[2];
    const float* b1 = (const float*)d_in[3];
    const float* W2 = (const float*)d_in[4];
    const float* b2 = (const float*)d_in[5];
    const float* W3 = (const float*)d_in[6];
    const float* b3 = (const float*)d_in[7];
    float* out = (float*)d_out;

    int E = in_sizes[1] / 2;
    if (E > NE) E = NE;

    k_init<<<(NN + 255) / 256, 256>>>(ei, E);
    k_hist<<<2048, 256>>>(ei, E);
    k_fin<<<(NN + 255) / 256, 256>>>(x);
    k_scatter<<<2048, 256>>>(ei, E);

    int a3N = (NN * 16 + 255) / 256;      // 16-lane-group grid

    k_l1<<<NBLK, 256>>>(x, W1, b1, W2);   // layer 1 (no gather) + layer 2 transform
    k_agg2<<<NBLK, 256>>>(x, b2, W3);     // layer 2 agg + layer 3 transform
    k_agg3<<<a3N, 256>>>(b3, out);        // layer 3 agg -> output
}

// round 14
// speedup vs baseline: 1.2143x; 1.2143x over previous
#include <cuda_runtime.h>
#include <cuda_fp16.h>

#define NN 200000
#define NE 3200000
#define F  30
#define FS 32          // padded feature stride
#define PAD 64         // padded CSR slots per node (max deg ~36 for Poisson(16))
#define NBLK 1184      // persistent grid (8 blocks/SM x 148 SMs)

// ---- scratch (device globals; no allocation allowed) ----
__device__ int    g_is64;
__device__ int    g_deg[NN];
__device__ int    g_cursor[NN];
__device__ float  g_dinv[NN];
__device__ float  g_xs[NN * 2];      // x * dinv (layer-1 aggregation operand)
__device__ int    g_csr[NN * PAD];   // padded CSR: node d owns [d*PAD, d*PAD+deg)
__device__ __half g_feat[NN * FS];   // layer-2 pre-scaled features (fp16, 64B rows)
__device__ float  g_scal[NN];        // layer-3 scalar features

// ---------------- init: cursor bases + dtype detect ----------------

__global__ void k_init(const void* __restrict__ ei, int E) {
    int i = blockIdx.x * blockDim.x + threadIdx.x;
    if (i < NN) g_cursor[i] = i * PAD;
    if (i == 0) {
        const long long* p = (const long long*)ei;
        int ok64 = 1;
        int n = (E < 64) ? E : 64;
        for (int k = 0; k < n; k++) {
            long long v = p[k];
            if (v < 0 || v >= NN) { ok64 = 0; break; }
        }
        g_is64 = ok64;
    }
}

// ---------------- scatter into padded CSR (converts inline) ----------------

__global__ void k_scatter(const void* __restrict__ ei, int E) {
    int is64 = g_is64;
    const long long* p64 = (const long long*)ei;
    const int*       p32 = (const int*)ei;
    for (int e = blockIdx.x * blockDim.x + threadIdx.x; e < E;
         e += gridDim.x * blockDim.x) {
        int s, d;
        if (is64) { s = (int)p64[e]; d = (int)p64[E + e]; }
        else      { s = p32[e];      d = p32[E + e]; }
        if ((unsigned)s >= NN) s = 0;
        if ((unsigned)d >= NN) d = 0;
        int pos = atomicAdd(&g_cursor[d], 1);
        if (pos < (d + 1) * PAD) g_csr[pos] = s;   // overflow guard (p ~ 0)
    }
}

// ---------------- finalize: deg, dinv, xs ----------------

__global__ void k_fin(const float* __restrict__ x) {
    int i = blockIdx.x * blockDim.x + threadIdx.x;
    if (i >= NN) return;
    int dg = g_cursor[i] - i * PAD;
    if (dg > PAD) dg = PAD;
    g_deg[i] = dg;
    float di = rsqrtf((float)(dg + 1));   // +1 self-loop
    g_dinv[i] = di;
    g_xs[2 * i]     = x[2 * i]     * di;
    g_xs[2 * i + 1] = x[2 * i + 1] * di;
}

// ---------------- layer 1 agg (input space) + fused layer-2 transform ------
// Persistent; TWO nodes per warp-iteration, interleaved register streams.

__global__ void __launch_bounds__(256)
k_agg1(const float* __restrict__ x, const float* __restrict__ W1,
       const float* __restrict__ b1, const float* __restrict__ W2) {
    __shared__ float w1[64];
    __shared__ float bb[32];
    __shared__ float w2[32 * 30];
    if (threadIdx.x < 60) w1[threadIdx.x] = W1[threadIdx.x];
    if (threadIdx.x < 30) bb[threadIdx.x] = b1[threadIdx.x];
    for (int j = threadIdx.x; j < 960; j += blockDim.x) w2[j] = W2[j];
    __syncthreads();

    int w = threadIdx.x >> 5;
    int lane = threadIdx.x & 31;
    int f = (lane < F) ? lane : 0;
    const int STRIDE = NBLK << 3;

    for (int d0 = (blockIdx.x << 3) + w; d0 < NN; d0 += 2 * STRIDE) {
        int d1 = d0 + STRIDE;
        bool v1 = (d1 < NN);

        int cnt0 = g_deg[d0];
        int cnt1 = v1 ? g_deg[d1] : 0;
        int base0 = d0 * PAD, base1 = d1 * PAD;
        int mx = max(cnt0, cnt1);

        float a00 = 0.f, a01 = 0.f, a10 = 0.f, a11 = 0.f;
        for (int i = lane; i < mx; i += 32) {
            if (i < cnt0) {
                float2 v = ((const float2*)g_xs)[g_csr[base0 + i]];
                a00 += v.x; a01 += v.y;
            }
            if (i < cnt1) {
                float2 v = ((const float2*)g_xs)[g_csr[base1 + i]];
                a10 += v.x; a11 += v.y;
            }
        }
#pragma unroll
        for (int st = 16; st > 0; st >>= 1) {
            a00 += __shfl_xor_sync(0xffffffffu, a00, st);
            a01 += __shfl_xor_sync(0xffffffffu, a01, st);
            a10 += __shfl_xor_sync(0xffffffffu, a10, st);
            a11 += __shfl_xor_sync(0xffffffffu, a11, st);
        }

        float2 self0 = ((const float2*)g_xs)[d0];
        float  di0   = g_dinv[d0];
        float s00 = (a00 + self0.x) * di0;
        float s01 = (a01 + self0.y) * di0;

        float2 self1 = v1 ? ((const float2*)g_xs)[d1] : make_float2(0.f, 0.f);
        float  di1   = v1 ? g_dinv[d1] : 0.f;
        float s10 = (a10 + self1.x) * di1;
        float s11 = (a11 + self1.y) * di1;

        float cat0, cat1;
        if (lane < F) {
            cat0 = fmaxf(fmaf(s00, w1[lane], fmaf(s01, w1[30 + lane], bb[lane])), 0.f);
            cat1 = fmaxf(fmaf(s10, w1[lane], fmaf(s11, w1[30 + lane], bb[lane])), 0.f);
        } else {
            cat0 = x[2 * d0 + (lane - 30)];
            cat1 = v1 ? x[2 * d1 + (lane - 30)] : 0.f;
        }

        float acc0 = 0.f, acc1 = 0.f;
#pragma unroll
        for (int k = 0; k < 32; k++) {
            float wk = w2[k * 30 + f];
            float c0 = __shfl_sync(0xffffffffu, cat0, k);
            float c1 = __shfl_sync(0xffffffffu, cat1, k);
            acc0 = fmaf(c0, wk, acc0);
            acc1 = fmaf(c1, wk, acc1);
        }
        g_feat[d0 * FS + lane] = __float2half((lane < F) ? acc0 * di0 : 0.f);
        if (v1)
            g_feat[d1 * FS + lane] = __float2half((lane < F) ? acc1 * di1 : 0.f);
    }
}

// ---------------- layer 2 agg (persistent, smem idx) + layer-3 transform ---

__global__ void __launch_bounds__(256)
k_agg2(const float* __restrict__ x, const float* __restrict__ b2,
       const float* __restrict__ W3) {
    __shared__ float bb[32];
    __shared__ float w3[32];
    __shared__ int   sidx[8][PAD];
    if (threadIdx.x < 30) bb[threadIdx.x] = b2[threadIdx.x];
    if (threadIdx.x < 32) w3[threadIdx.x] = W3[threadIdx.x];
    __syncthreads();

    int w = threadIdx.x >> 5;
    int lane = threadIdx.x & 31;

    for (int d = (blockIdx.x << 3) + w; d < NN; d += (NBLK << 3)) {
        int start = d * PAD, cnt = g_deg[d];
        if (lane < cnt) sidx[w][lane] = g_csr[start + lane];
        if (lane + 32 < cnt) sidx[w][lane + 32] = g_csr[start + lane + 32];
        __syncwarp();

        float acc0 = __half2float(g_feat[d * FS + lane]);   // self-loop term
        float acc1 = 0.f;
        int j = 0;
        for (; j + 1 < cnt; j += 2) {
            int s0 = sidx[w][j];
            int s1 = sidx[w][j + 1];
            acc0 += __half2float(g_feat[s0 * FS + lane]);
            acc1 += __half2float(g_feat[s1 * FS + lane]);
        }
        if (j < cnt) acc0 += __half2float(g_feat[sidx[w][j] * FS + lane]);
        float acc = acc0 + acc1;

        float di = g_dinv[d];
        float cat;
        if (lane < F) cat = fmaxf(fmaf(acc, di, bb[lane]), 0.f);
        else          cat = x[2 * d + (lane - 30)];

        float p = cat * w3[lane];
#pragma unroll
        for (int st = 16; st > 0; st >>= 1)
            p += __shfl_xor_sync(0xffffffffu, p, st);
        if (lane == 0) g_scal[d] = p * di;
        __syncwarp();
    }
}

// ---------------- layer 3 aggregation (16-lane group per node) -------------

__global__ void k_agg3(const float* __restrict__ b3, float* __restrict__ out) {
    int d = (blockIdx.x * blockDim.x + threadIdx.x) >> 4;
    int lane = threadIdx.x & 15;
    int gb = threadIdx.x & 16;
    unsigned gmask = 0xffffu << gb;
    if (d >= NN) return;
    int start = d * PAD, cnt = g_deg[d];
    float acc = 0.f;
    for (int idx = lane; idx < cnt; idx += 16)
        acc += g_scal[g_csr[start + idx]];
#pragma unroll
    for (int st = 8; st > 0; st >>= 1)
        acc += __shfl_xor_sync(gmask, acc, st);
    if (lane == 0) out[d] = g_dinv[d] * (acc + g_scal[d]) + b3[0];
}

// ---------------- launch ----------------

extern "C" void kernel_launch(void* const* d_in, const int* in_sizes, int n_in,
                              void* d_out, int out_size) {
    const float* x  = (const float*)d_in[0];
    const void*  ei = d_in[1];
    const float* W1 = (const float*)d_in[2];
    const float* b1 = (const float*)d_in[3];
    const float* W2 = (const float*)d_in[4];
    const float* b2 = (const float*)d_in[5];
    const float* W3 = (const float*)d_in[6];
    const float* b3 = (const float*)d_in[7];
    float* out = (float*)d_out;

    int E = in_sizes[1] / 2;
    if (E > NE) E = NE;

    k_init<<<(NN + 255) / 256, 256>>>(ei, E);
    k_scatter<<<2048, 256>>>(ei, E);
    k_fin<<<(NN + 255) / 256, 256>>>(x);

    int a3N = (NN * 16 + 255) / 256;      // 16-lane-group grid

    k_agg1<<<NBLK, 256>>>(x, W1, b1, W2); // layer 1 agg + layer 2 transform
    k_agg2<<<NBLK, 256>>>(x, b2, W3);     // layer 2 agg + layer 3 transform
    k_agg3<<<a3N, 256>>>(b3, out);        // layer 3 agg -> output
}